// round 1
// baseline (speedup 1.0000x reference)
#include <cuda_runtime.h>
#include <math.h>

#define BB 2
#define SS 2048
#define HH 1024
#define NHH 16
#define HDD 64
#define MM (BB*SS)          // 4096
#define Y_SIZE (BB*SS*HH)   // 4194304

// ---- scratch (no allocation allowed; device globals) ----
__device__ float g_Q[MM*HH];
__device__ float g_K[MM*HH];
__device__ float g_V[MM*HH];
__device__ float g_AO[MM*HH];
__device__ float g_X[MM*HH];

// ============================================================
// C[M,N] = A[M,K] @ W[N,K]^T  (+ optional residual, same shape as C)
// 64x64 tile, k-chunk 32. smem layout [kk][m] padded to 65 (conflict-free).
// ============================================================
__global__ void gemm_bt_kernel(const float* __restrict__ A,
                               const float* __restrict__ W,
                               float* __restrict__ C,
                               const float* __restrict__ res,
                               int Mdim, int Ndim, int Kdim) {
    __shared__ float As[32 * 65];
    __shared__ float Ws[32 * 65];
    const int bm = blockIdx.y * 64;
    const int bn = blockIdx.x * 64;
    const int tid = threadIdx.x;
    const int tm = (tid >> 4) << 2;   // 0..60
    const int tn = (tid & 15) << 2;   // 0..60

    float acc[4][4];
#pragma unroll
    for (int i = 0; i < 4; i++)
#pragma unroll
        for (int j = 0; j < 4; j++) acc[i][j] = 0.f;

    for (int k0 = 0; k0 < Kdim; k0 += 32) {
#pragma unroll 4
        for (int i = tid; i < 64 * 32; i += 256) {
            int m = i >> 5, kk = i & 31;
            As[kk * 65 + m] = A[(size_t)(bm + m) * Kdim + k0 + kk];
        }
#pragma unroll 4
        for (int i = tid; i < 64 * 32; i += 256) {
            int n = i >> 5, kk = i & 31;
            Ws[kk * 65 + n] = W[(size_t)(bn + n) * Kdim + k0 + kk];
        }
        __syncthreads();
#pragma unroll
        for (int kk = 0; kk < 32; kk++) {
            float a0 = As[kk * 65 + tm + 0];
            float a1 = As[kk * 65 + tm + 1];
            float a2 = As[kk * 65 + tm + 2];
            float a3 = As[kk * 65 + tm + 3];
            float b0 = Ws[kk * 65 + tn + 0];
            float b1 = Ws[kk * 65 + tn + 1];
            float b2 = Ws[kk * 65 + tn + 2];
            float b3 = Ws[kk * 65 + tn + 3];
            acc[0][0] += a0 * b0; acc[0][1] += a0 * b1; acc[0][2] += a0 * b2; acc[0][3] += a0 * b3;
            acc[1][0] += a1 * b0; acc[1][1] += a1 * b1; acc[1][2] += a1 * b2; acc[1][3] += a1 * b3;
            acc[2][0] += a2 * b0; acc[2][1] += a2 * b1; acc[2][2] += a2 * b2; acc[2][3] += a2 * b3;
            acc[3][0] += a3 * b0; acc[3][1] += a3 * b1; acc[3][2] += a3 * b2; acc[3][3] += a3 * b3;
        }
        __syncthreads();
    }

#pragma unroll
    for (int i = 0; i < 4; i++) {
#pragma unroll
        for (int j = 0; j < 4; j++) {
            size_t idx = (size_t)(bm + tm + i) * Ndim + bn + tn + j;
            float v = acc[i][j];
            if (res) v += res[idx];
            C[idx] = v;
        }
    }
}

// ============================================================
// Fused scores (QK^T * 1/sqrt(HD)) + mask + row softmax.
// Block: 8 q-rows of one (b,h); full row of S=2048 scores kept in smem.
// Writes attn_dist directly to d_out region.
// ============================================================
__global__ void scores_softmax_kernel(const float* __restrict__ Qb,
                                      const float* __restrict__ Kb,
                                      const float* __restrict__ mask,
                                      float* __restrict__ attn) {
    extern __shared__ float sm[];
    float* Ss = sm;                  // [8][2048]
    float* Qs = Ss + 8 * 2048;       // [8][64]
    float* Ks = Qs + 8 * 64;         // [64][65] stored as [d][k], pad 65

    const int b = blockIdx.z, h = blockIdx.y;
    const int q0 = blockIdx.x * 8;
    const int tid = threadIdx.x;

    for (int i = tid; i < 8 * 64; i += 256) {
        int r = i >> 6, d = i & 63;
        Qs[i] = Qb[(size_t)(b * SS + q0 + r) * HH + h * HDD + d];
    }

    const int qi = tid >> 5;          // 0..7
    const int kj = (tid & 31) * 2;    // 0..62

    for (int k0 = 0; k0 < SS; k0 += 64) {
        __syncthreads();
        for (int i = tid; i < 64 * 64; i += 256) {
            int r = i >> 6, d = i & 63;   // r = k index, d = headdim
            Ks[d * 65 + r] = Kb[(size_t)(b * SS + k0 + r) * HH + h * HDD + d];
        }
        __syncthreads();

        float a0 = 0.f, a1 = 0.f;
#pragma unroll
        for (int d = 0; d < 64; d++) {
            float qv = Qs[qi * 64 + d];
            a0 += qv * Ks[d * 65 + kj];
            a1 += qv * Ks[d * 65 + kj + 1];
        }
        const float* mrow = mask + ((size_t)b * SS + (q0 + qi)) * SS + k0;
        float m0 = mrow[kj], m1 = mrow[kj + 1];
        Ss[qi * 2048 + k0 + kj]     = (m0 == 0.f) ? -1e9f : a0 * 0.125f;
        Ss[qi * 2048 + k0 + kj + 1] = (m1 == 0.f) ? -1e9f : a1 * 0.125f;
    }
    __syncthreads();

    // softmax: one warp per row
    const int warp = tid >> 5, lane = tid & 31;
    const int row = warp;
    float mx = -INFINITY;
    for (int c = lane; c < SS; c += 32) mx = fmaxf(mx, Ss[row * 2048 + c]);
#pragma unroll
    for (int o = 16; o; o >>= 1) mx = fmaxf(mx, __shfl_xor_sync(0xffffffffu, mx, o));
    float sum = 0.f;
    for (int c = lane; c < SS; c += 32) {
        float e = __expf(Ss[row * 2048 + c] - mx);
        Ss[row * 2048 + c] = e;
        sum += e;
    }
#pragma unroll
    for (int o = 16; o; o >>= 1) sum += __shfl_xor_sync(0xffffffffu, sum, o);
    float inv = 1.f / sum;
    float* arow = attn + ((size_t)((b * NHH + h) * SS + q0 + row)) * SS;
    for (int c = lane; c < SS; c += 32) arow[c] = Ss[row * 2048 + c] * inv;
}

// ============================================================
// out[b,h,q,d] = sum_k P[b,h,q,k] * V[b,h,k,d]; stored as (B,S,H) row-major.
// 64q x 64d tile, k streamed in chunks of 64.
// ============================================================
__global__ void av_kernel(const float* __restrict__ attn,
                          const float* __restrict__ Vb,
                          float* __restrict__ Ob) {
    __shared__ float Ps[64 * 64];   // [q][k]
    __shared__ float Vs[64 * 64];   // [k][d]
    const int b = blockIdx.z, h = blockIdx.y;
    const int q0 = blockIdx.x * 64;
    const int tid = threadIdx.x;
    const int tm = (tid >> 4) << 2;
    const int tn = (tid & 15) << 2;

    float acc[4][4];
#pragma unroll
    for (int i = 0; i < 4; i++)
#pragma unroll
        for (int j = 0; j < 4; j++) acc[i][j] = 0.f;

    for (int k0 = 0; k0 < SS; k0 += 64) {
#pragma unroll 4
        for (int i = tid; i < 4096; i += 256) {
            int q = i >> 6, c = i & 63;
            Ps[q * 64 + c] = attn[((size_t)((b * NHH + h) * SS + q0 + q)) * SS + k0 + c];
        }
#pragma unroll 4
        for (int i = tid; i < 4096; i += 256) {
            int r = i >> 6, c = i & 63;
            Vs[r * 64 + c] = Vb[(size_t)(b * SS + k0 + r) * HH + h * HDD + c];
        }
        __syncthreads();
#pragma unroll
        for (int kk = 0; kk < 64; kk++) {
            float a0 = Ps[(tm + 0) * 64 + kk];
            float a1 = Ps[(tm + 1) * 64 + kk];
            float a2 = Ps[(tm + 2) * 64 + kk];
            float a3 = Ps[(tm + 3) * 64 + kk];
            float4 bv = *(const float4*)&Vs[kk * 64 + tn];
            acc[0][0] += a0 * bv.x; acc[0][1] += a0 * bv.y; acc[0][2] += a0 * bv.z; acc[0][3] += a0 * bv.w;
            acc[1][0] += a1 * bv.x; acc[1][1] += a1 * bv.y; acc[1][2] += a1 * bv.z; acc[1][3] += a1 * bv.w;
            acc[2][0] += a2 * bv.x; acc[2][1] += a2 * bv.y; acc[2][2] += a2 * bv.z; acc[2][3] += a2 * bv.w;
            acc[3][0] += a3 * bv.x; acc[3][1] += a3 * bv.y; acc[3][2] += a3 * bv.z; acc[3][3] += a3 * bv.w;
        }
        __syncthreads();
    }
#pragma unroll
    for (int i = 0; i < 4; i++)
#pragma unroll
        for (int j = 0; j < 4; j++)
            Ob[(size_t)(b * SS + q0 + tm + i) * HH + h * HDD + tn + j] = acc[i][j];
}

// ============================================================
// LayerNorm per row (eps=1e-6): y = (x - mu)/sqrt(var+eps)*w + b
// ============================================================
__global__ void ln_kernel(const float* __restrict__ X,
                          const float* __restrict__ w,
                          const float* __restrict__ bias,
                          float* __restrict__ Y) {
    __shared__ float red[8];
    __shared__ float bc;
    const int row = blockIdx.x;
    const float* x = X + (size_t)row * HH;
    const int tid = threadIdx.x, lane = tid & 31, warp = tid >> 5;

    float s = 0.f;
    for (int c = tid; c < HH; c += 256) s += x[c];
#pragma unroll
    for (int o = 16; o; o >>= 1) s += __shfl_xor_sync(0xffffffffu, s, o);
    if (lane == 0) red[warp] = s;
    __syncthreads();
    if (tid == 0) {
        float t = 0.f;
        for (int i = 0; i < 8; i++) t += red[i];
        bc = t / HH;
    }
    __syncthreads();
    float mu = bc;

    float v = 0.f;
    for (int c = tid; c < HH; c += 256) { float d = x[c] - mu; v += d * d; }
#pragma unroll
    for (int o = 16; o; o >>= 1) v += __shfl_xor_sync(0xffffffffu, v, o);
    if (lane == 0) red[warp] = v;
    __syncthreads();
    if (tid == 0) {
        float t = 0.f;
        for (int i = 0; i < 8; i++) t += red[i];
        bc = rsqrtf(t / HH + 1e-6f);
    }
    __syncthreads();
    float inv = bc;

    for (int c = tid; c < HH; c += 256)
        Y[(size_t)row * HH + c] = (x[c] - mu) * inv * w[c] + bias[c];
}

// ============================================================
extern "C" void kernel_launch(void* const* d_in, const int* in_sizes, int n_in,
                              void* d_out, int out_size) {
    const float* enc  = (const float*)d_in[0];
    const float* mask = (const float*)d_in[1];
    const float* WQ   = (const float*)d_in[2];
    const float* WK   = (const float*)d_in[3];
    const float* WV   = (const float*)d_in[4];
    const float* WO   = (const float*)d_in[5];
    const float* lnw  = (const float*)d_in[6];
    const float* lnb  = (const float*)d_in[7];

    float* y    = (float*)d_out;              // (B,S,H)
    float* attn = y + (size_t)Y_SIZE;         // (B,NH,S,S)

    float *Qp, *Kp, *Vp, *Op, *Xp;
    cudaGetSymbolAddress((void**)&Qp, g_Q);
    cudaGetSymbolAddress((void**)&Kp, g_K);
    cudaGetSymbolAddress((void**)&Vp, g_V);
    cudaGetSymbolAddress((void**)&Op, g_AO);
    cudaGetSymbolAddress((void**)&Xp, g_X);

    dim3 gg(HH / 64, MM / 64);   // (16, 64)
    gemm_bt_kernel<<<gg, 256>>>(enc, WQ, Qp, nullptr, MM, HH, HH);
    gemm_bt_kernel<<<gg, 256>>>(enc, WK, Kp, nullptr, MM, HH, HH);
    gemm_bt_kernel<<<gg, 256>>>(enc, WV, Vp, nullptr, MM, HH, HH);

    const int smem_bytes = (8 * 2048 + 8 * 64 + 64 * 65) * (int)sizeof(float); // 84224
    cudaFuncSetAttribute(scores_softmax_kernel,
                         cudaFuncAttributeMaxDynamicSharedMemorySize, smem_bytes);
    scores_softmax_kernel<<<dim3(SS / 8, NHH, BB), 256, smem_bytes>>>(Qp, Kp, mask, attn);

    av_kernel<<<dim3(SS / 64, NHH, BB), 256>>>(attn, Vp, Op);

    gemm_bt_kernel<<<gg, 256>>>(Op, WO, Xp, enc, MM, HH, HH);

    ln_kernel<<<MM, 256>>>(Xp, lnw, lnb, y);
}

// round 3
// speedup vs baseline: 1.1906x; 1.1906x over previous
#include <cuda_runtime.h>
#include <math.h>
#include <stdint.h>

#define BB 2
#define SS 2048
#define HH 1024
#define NHH 16
#define HDD 64
#define MM (BB*SS)          // 4096
#define Y_SIZE (BB*SS*HH)   // 4194304

// ---- scratch (no allocation allowed; device globals) ----
__device__ float g_Q[MM*HH];
__device__ float g_K[MM*HH];
__device__ float g_V[MM*HH];
__device__ float g_AO[MM*HH];
__device__ float g_X[MM*HH];

// ============================================================
// tf32 warp-MMA GEMM: C[4096,1024] = A[4096,1024] @ W[1024,1024]^T (+res)
// Block 256 thr (8 warps, 2x4), tile 128x128, k-chunk 16, double-buffered.
// mma.sync.m16n8k8.tf32: warp tile 64x32 = 4x4 mma tiles.
// smem stride 20 floats (conflict-free for frag loads, float4-aligned).
// ============================================================
__device__ __forceinline__ uint32_t f2tf32(float v) {
    uint32_t r;
    asm("cvt.rna.tf32.f32 %0, %1;" : "=r"(r) : "f"(v));
    return r;
}

__global__ void __launch_bounds__(256, 2)
gemm_mma_kernel(const float* __restrict__ A, const float* __restrict__ W,
                float* __restrict__ C, const float* __restrict__ res) {
    __shared__ float As[2][128 * 20];
    __shared__ float Ws[2][128 * 20];
    const int tid = threadIdx.x;
    const int wid = tid >> 5, lane = tid & 31;
    const int wm = wid >> 2, wn = wid & 3;        // 2 x 4 warp grid
    const int bm = blockIdx.y * 128, bn = blockIdx.x * 128;
    const int g = lane >> 2, t = lane & 3;

    // gmem->smem mapping: p in [0,512): row = p>>2 (0..127), qc = p&3 (float4 col)
    const int p0 = tid, p1 = tid + 256;
    const int r0 = p0 >> 2, q0 = (p0 & 3) * 4;
    const int r1 = p1 >> 2, q1 = (p1 & 3) * 4;
    const float* Arow0 = A + (size_t)(bm + r0) * 1024 + q0;
    const float* Arow1 = A + (size_t)(bm + r1) * 1024 + q1;
    const float* Wrow0 = W + (size_t)(bn + r0) * 1024 + q0;
    const float* Wrow1 = W + (size_t)(bn + r1) * 1024 + q1;
    const int s0 = r0 * 20 + q0, s1 = r1 * 20 + q1;

    float acc[4][4][4];
#pragma unroll
    for (int i = 0; i < 4; i++)
#pragma unroll
        for (int j = 0; j < 4; j++)
#pragma unroll
            for (int q = 0; q < 4; q++) acc[i][j][q] = 0.f;

    // prologue: chunk 0
    {
        float4 va0 = *(const float4*)(Arow0);
        float4 va1 = *(const float4*)(Arow1);
        float4 vw0 = *(const float4*)(Wrow0);
        float4 vw1 = *(const float4*)(Wrow1);
        uint32_t* a0 = (uint32_t*)&As[0][s0];
        a0[0]=f2tf32(va0.x); a0[1]=f2tf32(va0.y); a0[2]=f2tf32(va0.z); a0[3]=f2tf32(va0.w);
        uint32_t* a1 = (uint32_t*)&As[0][s1];
        a1[0]=f2tf32(va1.x); a1[1]=f2tf32(va1.y); a1[2]=f2tf32(va1.z); a1[3]=f2tf32(va1.w);
        uint32_t* w0 = (uint32_t*)&Ws[0][s0];
        w0[0]=f2tf32(vw0.x); w0[1]=f2tf32(vw0.y); w0[2]=f2tf32(vw0.z); w0[3]=f2tf32(vw0.w);
        uint32_t* w1 = (uint32_t*)&Ws[0][s1];
        w1[0]=f2tf32(vw1.x); w1[1]=f2tf32(vw1.y); w1[2]=f2tf32(vw1.z); w1[3]=f2tf32(vw1.w);
    }
    __syncthreads();

    for (int c = 0; c < 64; c++) {
        const int buf = c & 1;
        float4 ra0, ra1, rw0, rw1;
        if (c < 63) {
            const int k0 = (c + 1) * 16;
            ra0 = *(const float4*)(Arow0 + k0);
            ra1 = *(const float4*)(Arow1 + k0);
            rw0 = *(const float4*)(Wrow0 + k0);
            rw1 = *(const float4*)(Wrow1 + k0);
        }

#pragma unroll
        for (int ks = 0; ks < 2; ks++) {
            const int kk = ks * 8;
            uint32_t af[4][4], bf[4][2];
#pragma unroll
            for (int im = 0; im < 4; im++) {
                const int m0 = wm * 64 + im * 16;
                af[im][0] = __float_as_uint(As[buf][(m0 + g) * 20 + kk + t]);
                af[im][1] = __float_as_uint(As[buf][(m0 + g + 8) * 20 + kk + t]);
                af[im][2] = __float_as_uint(As[buf][(m0 + g) * 20 + kk + t + 4]);
                af[im][3] = __float_as_uint(As[buf][(m0 + g + 8) * 20 + kk + t + 4]);
            }
#pragma unroll
            for (int jn = 0; jn < 4; jn++) {
                const int n0 = wn * 32 + jn * 8;
                bf[jn][0] = __float_as_uint(Ws[buf][(n0 + g) * 20 + kk + t]);
                bf[jn][1] = __float_as_uint(Ws[buf][(n0 + g) * 20 + kk + t + 4]);
            }
#pragma unroll
            for (int im = 0; im < 4; im++)
#pragma unroll
                for (int jn = 0; jn < 4; jn++) {
                    asm volatile(
                        "mma.sync.aligned.m16n8k8.row.col.f32.tf32.tf32.f32 "
                        "{%0,%1,%2,%3}, {%4,%5,%6,%7}, {%8,%9}, {%0,%1,%2,%3};"
                        : "+f"(acc[im][jn][0]), "+f"(acc[im][jn][1]),
                          "+f"(acc[im][jn][2]), "+f"(acc[im][jn][3])
                        : "r"(af[im][0]), "r"(af[im][1]), "r"(af[im][2]), "r"(af[im][3]),
                          "r"(bf[jn][0]), "r"(bf[jn][1]));
                }
        }

        if (c < 63) {
            const int nxt = buf ^ 1;
            uint32_t* a0 = (uint32_t*)&As[nxt][s0];
            a0[0]=f2tf32(ra0.x); a0[1]=f2tf32(ra0.y); a0[2]=f2tf32(ra0.z); a0[3]=f2tf32(ra0.w);
            uint32_t* a1 = (uint32_t*)&As[nxt][s1];
            a1[0]=f2tf32(ra1.x); a1[1]=f2tf32(ra1.y); a1[2]=f2tf32(ra1.z); a1[3]=f2tf32(ra1.w);
            uint32_t* w0 = (uint32_t*)&Ws[nxt][s0];
            w0[0]=f2tf32(rw0.x); w0[1]=f2tf32(rw0.y); w0[2]=f2tf32(rw0.z); w0[3]=f2tf32(rw0.w);
            uint32_t* w1 = (uint32_t*)&Ws[nxt][s1];
            w1[0]=f2tf32(rw1.x); w1[1]=f2tf32(rw1.y); w1[2]=f2tf32(rw1.z); w1[3]=f2tf32(rw1.w);
        }
        __syncthreads();
    }

    // epilogue: c0:(g,2t) c1:(g,2t+1) c2:(g+8,2t) c3:(g+8,2t+1)
#pragma unroll
    for (int im = 0; im < 4; im++) {
        const int rowA = bm + wm * 64 + im * 16 + g;
        const int rowB = rowA + 8;
#pragma unroll
        for (int jn = 0; jn < 4; jn++) {
            const int col = bn + wn * 32 + jn * 8 + 2 * t;
            float2 vA = make_float2(acc[im][jn][0], acc[im][jn][1]);
            float2 vB = make_float2(acc[im][jn][2], acc[im][jn][3]);
            if (res) {
                float2 rA = *(const float2*)(res + (size_t)rowA * 1024 + col);
                float2 rB = *(const float2*)(res + (size_t)rowB * 1024 + col);
                vA.x += rA.x; vA.y += rA.y; vB.x += rB.x; vB.y += rB.y;
            }
            *(float2*)(C + (size_t)rowA * 1024 + col) = vA;
            *(float2*)(C + (size_t)rowB * 1024 + col) = vB;
        }
    }
}

// ============================================================
// Fused scores (QK^T * 1/sqrt(HD)) + mask + row softmax.
// ============================================================
__global__ void scores_softmax_kernel(const float* __restrict__ Qb,
                                      const float* __restrict__ Kb,
                                      const float* __restrict__ mask,
                                      float* __restrict__ attn) {
    extern __shared__ float sm[];
    float* Ss = sm;                  // [8][2048]
    float* Qs = Ss + 8 * 2048;       // [8][64]
    float* Ks = Qs + 8 * 64;         // [64][65]

    const int b = blockIdx.z, h = blockIdx.y;
    const int q0 = blockIdx.x * 8;
    const int tid = threadIdx.x;

    for (int i = tid; i < 8 * 64; i += 256) {
        int r = i >> 6, d = i & 63;
        Qs[i] = Qb[(size_t)(b * SS + q0 + r) * HH + h * HDD + d];
    }

    const int qi = tid >> 5;
    const int kj = (tid & 31) * 2;

    for (int k0 = 0; k0 < SS; k0 += 64) {
        __syncthreads();
        for (int i = tid; i < 64 * 64; i += 256) {
            int r = i >> 6, d = i & 63;
            Ks[d * 65 + r] = Kb[(size_t)(b * SS + k0 + r) * HH + h * HDD + d];
        }
        __syncthreads();

        float a0 = 0.f, a1 = 0.f;
#pragma unroll
        for (int d = 0; d < 64; d++) {
            float qv = Qs[qi * 64 + d];
            a0 += qv * Ks[d * 65 + kj];
            a1 += qv * Ks[d * 65 + kj + 1];
        }
        const float* mrow = mask + ((size_t)b * SS + (q0 + qi)) * SS + k0;
        float m0 = mrow[kj], m1 = mrow[kj + 1];
        Ss[qi * 2048 + k0 + kj]     = (m0 == 0.f) ? -1e9f : a0 * 0.125f;
        Ss[qi * 2048 + k0 + kj + 1] = (m1 == 0.f) ? -1e9f : a1 * 0.125f;
    }
    __syncthreads();

    const int warp = tid >> 5, lane = tid & 31;
    const int row = warp;
    float mx = -INFINITY;
    for (int c = lane; c < SS; c += 32) mx = fmaxf(mx, Ss[row * 2048 + c]);
#pragma unroll
    for (int o = 16; o; o >>= 1) mx = fmaxf(mx, __shfl_xor_sync(0xffffffffu, mx, o));
    float sum = 0.f;
    for (int c = lane; c < SS; c += 32) {
        float e = __expf(Ss[row * 2048 + c] - mx);
        Ss[row * 2048 + c] = e;
        sum += e;
    }
#pragma unroll
    for (int o = 16; o; o >>= 1) sum += __shfl_xor_sync(0xffffffffu, sum, o);
    float inv = 1.f / sum;
    float* arow = attn + ((size_t)((b * NHH + h) * SS + q0 + row)) * SS;
    for (int c = lane; c < SS; c += 32) arow[c] = Ss[row * 2048 + c] * inv;
}

// ============================================================
// AV kernel
// ============================================================
__global__ void av_kernel(const float* __restrict__ attn,
                          const float* __restrict__ Vb,
                          float* __restrict__ Ob) {
    __shared__ float Ps[64 * 64];
    __shared__ float Vs[64 * 64];
    const int b = blockIdx.z, h = blockIdx.y;
    const int q0 = blockIdx.x * 64;
    const int tid = threadIdx.x;
    const int tm = (tid >> 4) << 2;
    const int tn = (tid & 15) << 2;

    float acc[4][4];
#pragma unroll
    for (int i = 0; i < 4; i++)
#pragma unroll
        for (int j = 0; j < 4; j++) acc[i][j] = 0.f;

    for (int k0 = 0; k0 < SS; k0 += 64) {
#pragma unroll 4
        for (int i = tid; i < 4096; i += 256) {
            int q = i >> 6, c = i & 63;
            Ps[q * 64 + c] = attn[((size_t)((b * NHH + h) * SS + q0 + q)) * SS + k0 + c];
        }
#pragma unroll 4
        for (int i = tid; i < 4096; i += 256) {
            int r = i >> 6, c = i & 63;
            Vs[r * 64 + c] = Vb[(size_t)(b * SS + k0 + r) * HH + h * HDD + c];
        }
        __syncthreads();
#pragma unroll
        for (int kk = 0; kk < 64; kk++) {
            float a0 = Ps[(tm + 0) * 64 + kk];
            float a1 = Ps[(tm + 1) * 64 + kk];
            float a2 = Ps[(tm + 2) * 64 + kk];
            float a3 = Ps[(tm + 3) * 64 + kk];
            float4 bv = *(const float4*)&Vs[kk * 64 + tn];
            acc[0][0] += a0 * bv.x; acc[0][1] += a0 * bv.y; acc[0][2] += a0 * bv.z; acc[0][3] += a0 * bv.w;
            acc[1][0] += a1 * bv.x; acc[1][1] += a1 * bv.y; acc[1][2] += a1 * bv.z; acc[1][3] += a1 * bv.w;
            acc[2][0] += a2 * bv.x; acc[2][1] += a2 * bv.y; acc[2][2] += a2 * bv.z; acc[2][3] += a2 * bv.w;
            acc[3][0] += a3 * bv.x; acc[3][1] += a3 * bv.y; acc[3][2] += a3 * bv.z; acc[3][3] += a3 * bv.w;
        }
        __syncthreads();
    }
#pragma unroll
    for (int i = 0; i < 4; i++)
#pragma unroll
        for (int j = 0; j < 4; j++)
            Ob[(size_t)(b * SS + q0 + tm + i) * HH + h * HDD + tn + j] = acc[i][j];
}

// ============================================================
// LayerNorm
// ============================================================
__global__ void ln_kernel(const float* __restrict__ X,
                          const float* __restrict__ w,
                          const float* __restrict__ bias,
                          float* __restrict__ Y) {
    __shared__ float red[8];
    __shared__ float bc;
    const int row = blockIdx.x;
    const float* x = X + (size_t)row * HH;
    const int tid = threadIdx.x, lane = tid & 31, warp = tid >> 5;

    float s = 0.f;
    for (int c = tid; c < HH; c += 256) s += x[c];
#pragma unroll
    for (int o = 16; o; o >>= 1) s += __shfl_xor_sync(0xffffffffu, s, o);
    if (lane == 0) red[warp] = s;
    __syncthreads();
    if (tid == 0) {
        float tt = 0.f;
        for (int i = 0; i < 8; i++) tt += red[i];
        bc = tt / HH;
    }
    __syncthreads();
    float mu = bc;

    float v = 0.f;
    for (int c = tid; c < HH; c += 256) { float d = x[c] - mu; v += d * d; }
#pragma unroll
    for (int o = 16; o; o >>= 1) v += __shfl_xor_sync(0xffffffffu, v, o);
    if (lane == 0) red[warp] = v;
    __syncthreads();
    if (tid == 0) {
        float tt = 0.f;
        for (int i = 0; i < 8; i++) tt += red[i];
        bc = rsqrtf(tt / HH + 1e-6f);
    }
    __syncthreads();
    float inv = bc;

    for (int c = tid; c < HH; c += 256)
        Y[(size_t)row * HH + c] = (x[c] - mu) * inv * w[c] + bias[c];
}

// ============================================================
extern "C" void kernel_launch(void* const* d_in, const int* in_sizes, int n_in,
                              void* d_out, int out_size) {
    const float* enc  = (const float*)d_in[0];
    const float* mask = (const float*)d_in[1];
    const float* WQ   = (const float*)d_in[2];
    const float* WK   = (const float*)d_in[3];
    const float* WV   = (const float*)d_in[4];
    const float* WO   = (const float*)d_in[5];
    const float* lnw  = (const float*)d_in[6];
    const float* lnb  = (const float*)d_in[7];

    float* y    = (float*)d_out;              // (B,S,H)
    float* attn = y + (size_t)Y_SIZE;         // (B,NH,S,S)

    float *Qp, *Kp, *Vp, *Op, *Xp;
    cudaGetSymbolAddress((void**)&Qp, g_Q);
    cudaGetSymbolAddress((void**)&Kp, g_K);
    cudaGetSymbolAddress((void**)&Vp, g_V);
    cudaGetSymbolAddress((void**)&Op, g_AO);
    cudaGetSymbolAddress((void**)&Xp, g_X);

    dim3 gt(HH / 128, MM / 128);   // (8, 32)
    gemm_mma_kernel<<<gt, 256>>>(enc, WQ, Qp, nullptr);
    gemm_mma_kernel<<<gt, 256>>>(enc, WK, Kp, nullptr);
    gemm_mma_kernel<<<gt, 256>>>(enc, WV, Vp, nullptr);

    const int smem_bytes = (8 * 2048 + 8 * 64 + 64 * 65) * (int)sizeof(float); // 84224
    cudaFuncSetAttribute(scores_softmax_kernel,
                         cudaFuncAttributeMaxDynamicSharedMemorySize, smem_bytes);
    scores_softmax_kernel<<<dim3(SS / 8, NHH, BB), 256, smem_bytes>>>(Qp, Kp, mask, attn);

    av_kernel<<<dim3(SS / 64, NHH, BB), 256>>>(attn, Vp, Op);

    gemm_mma_kernel<<<gt, 256>>>(Op, WO, Xp, enc);

    ln_kernel<<<MM, 256>>>(Xp, lnw, lnb, y);
}

// round 4
// speedup vs baseline: 5.8622x; 4.9236x over previous
#include <cuda_runtime.h>
#include <math.h>
#include <stdint.h>

#define BB 2
#define SS 2048
#define HH 1024
#define NHH 16
#define HDD 64
#define MM (BB*SS)          // 4096
#define Y_SIZE (BB*SS*HH)   // 4194304

// ---- scratch (no allocation allowed; device globals) ----
__device__ float g_Q[MM*HH];
__device__ float g_K[MM*HH];
__device__ float g_V[MM*HH];
__device__ float g_AO[MM*HH];
__device__ float g_X[MM*HH];

__device__ __forceinline__ uint32_t f2tf32(float v) {
    uint32_t r;
    asm("cvt.rna.tf32.f32 %0, %1;" : "=r"(r) : "f"(v));
    return r;
}

#define MMA_TF32(acc, a0,a1,a2,a3, b0,b1) \
    asm volatile("mma.sync.aligned.m16n8k8.row.col.f32.tf32.tf32.f32 " \
        "{%0,%1,%2,%3}, {%4,%5,%6,%7}, {%8,%9}, {%0,%1,%2,%3};" \
        : "+f"((acc)[0]), "+f"((acc)[1]), "+f"((acc)[2]), "+f"((acc)[3]) \
        : "r"(a0), "r"(a1), "r"(a2), "r"(a3), "r"(b0), "r"(b1))

// ============================================================
// tf32 warp-MMA GEMM: C[4096,1024] = A[4096,1024] @ W[1024,1024]^T (+res)
// ============================================================
__global__ void __launch_bounds__(256, 2)
gemm_mma_kernel(const float* __restrict__ A, const float* __restrict__ W,
                float* __restrict__ C, const float* __restrict__ res) {
    __shared__ float As[2][128 * 20];
    __shared__ float Ws[2][128 * 20];
    const int tid = threadIdx.x;
    const int wid = tid >> 5, lane = tid & 31;
    const int wm = wid >> 2, wn = wid & 3;
    const int bm = blockIdx.y * 128, bn = blockIdx.x * 128;
    const int g = lane >> 2, t = lane & 3;

    const int p0 = tid, p1 = tid + 256;
    const int r0 = p0 >> 2, q0 = (p0 & 3) * 4;
    const int r1 = p1 >> 2, q1 = (p1 & 3) * 4;
    const float* Arow0 = A + (size_t)(bm + r0) * 1024 + q0;
    const float* Arow1 = A + (size_t)(bm + r1) * 1024 + q1;
    const float* Wrow0 = W + (size_t)(bn + r0) * 1024 + q0;
    const float* Wrow1 = W + (size_t)(bn + r1) * 1024 + q1;
    const int s0 = r0 * 20 + q0, s1 = r1 * 20 + q1;

    float acc[4][4][4];
#pragma unroll
    for (int i = 0; i < 4; i++)
#pragma unroll
        for (int j = 0; j < 4; j++)
#pragma unroll
            for (int q = 0; q < 4; q++) acc[i][j][q] = 0.f;

    {
        float4 va0 = *(const float4*)(Arow0);
        float4 va1 = *(const float4*)(Arow1);
        float4 vw0 = *(const float4*)(Wrow0);
        float4 vw1 = *(const float4*)(Wrow1);
        uint32_t* a0 = (uint32_t*)&As[0][s0];
        a0[0]=f2tf32(va0.x); a0[1]=f2tf32(va0.y); a0[2]=f2tf32(va0.z); a0[3]=f2tf32(va0.w);
        uint32_t* a1 = (uint32_t*)&As[0][s1];
        a1[0]=f2tf32(va1.x); a1[1]=f2tf32(va1.y); a1[2]=f2tf32(va1.z); a1[3]=f2tf32(va1.w);
        uint32_t* w0 = (uint32_t*)&Ws[0][s0];
        w0[0]=f2tf32(vw0.x); w0[1]=f2tf32(vw0.y); w0[2]=f2tf32(vw0.z); w0[3]=f2tf32(vw0.w);
        uint32_t* w1 = (uint32_t*)&Ws[0][s1];
        w1[0]=f2tf32(vw1.x); w1[1]=f2tf32(vw1.y); w1[2]=f2tf32(vw1.z); w1[3]=f2tf32(vw1.w);
    }
    __syncthreads();

    for (int c = 0; c < 64; c++) {
        const int buf = c & 1;
        float4 ra0, ra1, rw0, rw1;
        if (c < 63) {
            const int k0 = (c + 1) * 16;
            ra0 = *(const float4*)(Arow0 + k0);
            ra1 = *(const float4*)(Arow1 + k0);
            rw0 = *(const float4*)(Wrow0 + k0);
            rw1 = *(const float4*)(Wrow1 + k0);
        }

#pragma unroll
        for (int ks = 0; ks < 2; ks++) {
            const int kk = ks * 8;
            uint32_t af[4][4], bf[4][2];
#pragma unroll
            for (int im = 0; im < 4; im++) {
                const int m0 = wm * 64 + im * 16;
                af[im][0] = __float_as_uint(As[buf][(m0 + g) * 20 + kk + t]);
                af[im][1] = __float_as_uint(As[buf][(m0 + g + 8) * 20 + kk + t]);
                af[im][2] = __float_as_uint(As[buf][(m0 + g) * 20 + kk + t + 4]);
                af[im][3] = __float_as_uint(As[buf][(m0 + g + 8) * 20 + kk + t + 4]);
            }
#pragma unroll
            for (int jn = 0; jn < 4; jn++) {
                const int n0 = wn * 32 + jn * 8;
                bf[jn][0] = __float_as_uint(Ws[buf][(n0 + g) * 20 + kk + t]);
                bf[jn][1] = __float_as_uint(Ws[buf][(n0 + g) * 20 + kk + t + 4]);
            }
#pragma unroll
            for (int im = 0; im < 4; im++)
#pragma unroll
                for (int jn = 0; jn < 4; jn++)
                    MMA_TF32(acc[im][jn], af[im][0], af[im][1], af[im][2], af[im][3],
                             bf[jn][0], bf[jn][1]);
        }

        if (c < 63) {
            const int nxt = buf ^ 1;
            uint32_t* a0 = (uint32_t*)&As[nxt][s0];
            a0[0]=f2tf32(ra0.x); a0[1]=f2tf32(ra0.y); a0[2]=f2tf32(ra0.z); a0[3]=f2tf32(ra0.w);
            uint32_t* a1 = (uint32_t*)&As[nxt][s1];
            a1[0]=f2tf32(ra1.x); a1[1]=f2tf32(ra1.y); a1[2]=f2tf32(ra1.z); a1[3]=f2tf32(ra1.w);
            uint32_t* w0 = (uint32_t*)&Ws[nxt][s0];
            w0[0]=f2tf32(rw0.x); w0[1]=f2tf32(rw0.y); w0[2]=f2tf32(rw0.z); w0[3]=f2tf32(rw0.w);
            uint32_t* w1 = (uint32_t*)&Ws[nxt][s1];
            w1[0]=f2tf32(rw1.x); w1[1]=f2tf32(rw1.y); w1[2]=f2tf32(rw1.z); w1[3]=f2tf32(rw1.w);
        }
        __syncthreads();
    }

#pragma unroll
    for (int im = 0; im < 4; im++) {
        const int rowA = bm + wm * 64 + im * 16 + g;
        const int rowB = rowA + 8;
#pragma unroll
        for (int jn = 0; jn < 4; jn++) {
            const int col = bn + wn * 32 + jn * 8 + 2 * t;
            float2 vA = make_float2(acc[im][jn][0], acc[im][jn][1]);
            float2 vB = make_float2(acc[im][jn][2], acc[im][jn][3]);
            if (res) {
                float2 rA = *(const float2*)(res + (size_t)rowA * 1024 + col);
                float2 rB = *(const float2*)(res + (size_t)rowB * 1024 + col);
                vA.x += rA.x; vA.y += rA.y; vB.x += rB.x; vB.y += rB.y;
            }
            *(float2*)(C + (size_t)rowA * 1024 + col) = vA;
            *(float2*)(C + (size_t)rowB * 1024 + col) = vB;
        }
    }
}

// ============================================================
// Scores via MMA: raw = (Q K^T)*0.125 with mask -> attn buffer (unnormalized).
// Per (b,h): M=N tile 128x128, K=64 single-shot. 256 thr, 8 warps (2x4).
// ============================================================
__global__ void __launch_bounds__(256, 2)
scores_mma_kernel(const float* __restrict__ Qb, const float* __restrict__ Kb,
                  const float* __restrict__ mask, float* __restrict__ attn) {
    extern __shared__ float sm[];
    float* Qs = sm;               // 128 x 68
    float* Ks = sm + 128 * 68;    // 128 x 68
    const int tid = threadIdx.x;
    const int wid = tid >> 5, lane = tid & 31;
    const int wm = wid >> 2, wn = wid & 3;
    const int bh = blockIdx.z, b = bh >> 4, h = bh & 15;
    const int q0 = blockIdx.y * 128, n0b = blockIdx.x * 128;
    const int g = lane >> 2, t = lane & 3;

    const float* Qbase = Qb + ((size_t)(b * SS + q0)) * HH + h * HDD;
    const float* Kbase = Kb + ((size_t)(b * SS + n0b)) * HH + h * HDD;
#pragma unroll
    for (int j = 0; j < 8; j++) {
        int idx = tid + j * 256;          // 0..2047
        int r = idx >> 4, c4 = (idx & 15) * 4;
        float4 vq = *(const float4*)(Qbase + (size_t)r * HH + c4);
        uint32_t* q = (uint32_t*)&Qs[r * 68 + c4];
        q[0]=f2tf32(vq.x); q[1]=f2tf32(vq.y); q[2]=f2tf32(vq.z); q[3]=f2tf32(vq.w);
        float4 vk = *(const float4*)(Kbase + (size_t)r * HH + c4);
        uint32_t* k = (uint32_t*)&Ks[r * 68 + c4];
        k[0]=f2tf32(vk.x); k[1]=f2tf32(vk.y); k[2]=f2tf32(vk.z); k[3]=f2tf32(vk.w);
    }
    __syncthreads();

    float acc[4][4][4];
#pragma unroll
    for (int i = 0; i < 4; i++)
#pragma unroll
        for (int j = 0; j < 4; j++)
#pragma unroll
            for (int q = 0; q < 4; q++) acc[i][j][q] = 0.f;

#pragma unroll
    for (int ks = 0; ks < 8; ks++) {
        const int kk = ks * 8;
        uint32_t af[4][4], bf[4][2];
#pragma unroll
        for (int im = 0; im < 4; im++) {
            const int m0 = wm * 64 + im * 16;
            af[im][0] = __float_as_uint(Qs[(m0 + g) * 68 + kk + t]);
            af[im][1] = __float_as_uint(Qs[(m0 + g + 8) * 68 + kk + t]);
            af[im][2] = __float_as_uint(Qs[(m0 + g) * 68 + kk + t + 4]);
            af[im][3] = __float_as_uint(Qs[(m0 + g + 8) * 68 + kk + t + 4]);
        }
#pragma unroll
        for (int jn = 0; jn < 4; jn++) {
            const int n0 = wn * 32 + jn * 8;
            bf[jn][0] = __float_as_uint(Ks[(n0 + g) * 68 + kk + t]);
            bf[jn][1] = __float_as_uint(Ks[(n0 + g) * 68 + kk + t + 4]);
        }
#pragma unroll
        for (int im = 0; im < 4; im++)
#pragma unroll
            for (int jn = 0; jn < 4; jn++)
                MMA_TF32(acc[im][jn], af[im][0], af[im][1], af[im][2], af[im][3],
                         bf[jn][0], bf[jn][1]);
    }

#pragma unroll
    for (int im = 0; im < 4; im++) {
        const int rowA = q0 + wm * 64 + im * 16 + g;
        const int rowB = rowA + 8;
        const float* mA = mask + ((size_t)(b * SS + rowA)) * SS + n0b;
        const float* mB = mask + ((size_t)(b * SS + rowB)) * SS + n0b;
        float* aA = attn + ((size_t)((b * NHH + h) * SS + rowA)) * SS + n0b;
        float* aB = attn + ((size_t)((b * NHH + h) * SS + rowB)) * SS + n0b;
#pragma unroll
        for (int jn = 0; jn < 4; jn++) {
            const int col = wn * 32 + jn * 8 + 2 * t;
            float2 mvA = *(const float2*)(mA + col);
            float2 mvB = *(const float2*)(mB + col);
            float2 vA, vB;
            vA.x = (mvA.x == 0.f) ? -1e9f : acc[im][jn][0] * 0.125f;
            vA.y = (mvA.y == 0.f) ? -1e9f : acc[im][jn][1] * 0.125f;
            vB.x = (mvB.x == 0.f) ? -1e9f : acc[im][jn][2] * 0.125f;
            vB.y = (mvB.y == 0.f) ? -1e9f : acc[im][jn][3] * 0.125f;
            *(float2*)(aA + col) = vA;
            *(float2*)(aB + col) = vB;
        }
    }
}

// ============================================================
// Row softmax in-place on attn: 1 block per row, 256 thr, 8 floats/thread.
// ============================================================
__global__ void __launch_bounds__(256, 8)
softmax_kernel(float* __restrict__ attn) {
    __shared__ float red[8];
    float* p = attn + (size_t)blockIdx.x * SS;
    const int tid = threadIdx.x, lane = tid & 31, warp = tid >> 5;

    float4 v0 = *(const float4*)(p + tid * 4);
    float4 v1 = *(const float4*)(p + 1024 + tid * 4);

    float mx = fmaxf(fmaxf(fmaxf(v0.x, v0.y), fmaxf(v0.z, v0.w)),
                     fmaxf(fmaxf(v1.x, v1.y), fmaxf(v1.z, v1.w)));
#pragma unroll
    for (int o = 16; o; o >>= 1) mx = fmaxf(mx, __shfl_xor_sync(0xffffffffu, mx, o));
    if (lane == 0) red[warp] = mx;
    __syncthreads();
    float m = red[0];
#pragma unroll
    for (int i = 1; i < 8; i++) m = fmaxf(m, red[i]);

    v0.x = __expf(v0.x - m); v0.y = __expf(v0.y - m);
    v0.z = __expf(v0.z - m); v0.w = __expf(v0.w - m);
    v1.x = __expf(v1.x - m); v1.y = __expf(v1.y - m);
    v1.z = __expf(v1.z - m); v1.w = __expf(v1.w - m);

    float s = v0.x + v0.y + v0.z + v0.w + v1.x + v1.y + v1.z + v1.w;
#pragma unroll
    for (int o = 16; o; o >>= 1) s += __shfl_xor_sync(0xffffffffu, s, o);
    __syncthreads();
    if (lane == 0) red[warp] = s;
    __syncthreads();
    float tot = 0.f;
#pragma unroll
    for (int i = 0; i < 8; i++) tot += red[i];
    float inv = 1.f / tot;

    v0.x *= inv; v0.y *= inv; v0.z *= inv; v0.w *= inv;
    v1.x *= inv; v1.y *= inv; v1.z *= inv; v1.w *= inv;
    *(float4*)(p + tid * 4) = v0;
    *(float4*)(p + 1024 + tid * 4) = v1;
}

// ============================================================
// AV via MMA: O[128q x 64d] per block, K streamed in 64-chunks.
// 256 thr, 8 warps (4m x 2n), warp tile 32x32 (2x4 m16n8 tiles).
// V transposed in smem to [d][k] for the col-major B operand.
// ============================================================
__global__ void __launch_bounds__(256, 3)
av_mma_kernel(const float* __restrict__ attn, const float* __restrict__ Vb,
              float* __restrict__ Ob) {
    extern __shared__ float sm[];
    float* Ps = sm;               // 128 x 68
    float* Vs = sm + 128 * 68;    // 64 x 68
    const int tid = threadIdx.x;
    const int wid = tid >> 5, lane = tid & 31;
    const int wm = wid >> 1, wn = wid & 1;       // 4 x 2
    const int bh = blockIdx.y, b = bh >> 4, h = bh & 15;
    const int q0 = blockIdx.x * 128;
    const int g = lane >> 2, t = lane & 3;

    float acc[2][4][4];
#pragma unroll
    for (int i = 0; i < 2; i++)
#pragma unroll
        for (int j = 0; j < 4; j++)
#pragma unroll
            for (int q = 0; q < 4; q++) acc[i][j][q] = 0.f;

    const float* Pbase = attn + ((size_t)((b * NHH + h) * SS + q0)) * SS;
    const float* Vbase = Vb + ((size_t)(b * SS)) * HH + h * HDD;

    for (int k0 = 0; k0 < SS; k0 += 64) {
#pragma unroll
        for (int j = 0; j < 8; j++) {
            int idx = tid + j * 256;          // 0..2047
            int r = idx >> 4, c4 = (idx & 15) * 4;
            float4 v = *(const float4*)(Pbase + (size_t)r * SS + k0 + c4);
            uint32_t* q = (uint32_t*)&Ps[r * 68 + c4];
            q[0]=f2tf32(v.x); q[1]=f2tf32(v.y); q[2]=f2tf32(v.z); q[3]=f2tf32(v.w);
        }
#pragma unroll
        for (int j = 0; j < 4; j++) {
            int idx = tid + j * 256;          // 0..1023
            int r = idx >> 4, c4 = (idx & 15) * 4;   // r = k row, c4 = d col
            float4 v = *(const float4*)(Vbase + (size_t)(k0 + r) * HH + c4);
            Vs[(c4 + 0) * 68 + r] = __uint_as_float(f2tf32(v.x));
            Vs[(c4 + 1) * 68 + r] = __uint_as_float(f2tf32(v.y));
            Vs[(c4 + 2) * 68 + r] = __uint_as_float(f2tf32(v.z));
            Vs[(c4 + 3) * 68 + r] = __uint_as_float(f2tf32(v.w));
        }
        __syncthreads();

#pragma unroll
        for (int ks = 0; ks < 8; ks++) {
            const int kk = ks * 8;
            uint32_t af[2][4], bf[4][2];
#pragma unroll
            for (int im = 0; im < 2; im++) {
                const int m0 = wm * 32 + im * 16;
                af[im][0] = __float_as_uint(Ps[(m0 + g) * 68 + kk + t]);
                af[im][1] = __float_as_uint(Ps[(m0 + g + 8) * 68 + kk + t]);
                af[im][2] = __float_as_uint(Ps[(m0 + g) * 68 + kk + t + 4]);
                af[im][3] = __float_as_uint(Ps[(m0 + g + 8) * 68 + kk + t + 4]);
            }
#pragma unroll
            for (int jn = 0; jn < 4; jn++) {
                const int n0 = wn * 32 + jn * 8;
                bf[jn][0] = __float_as_uint(Vs[(n0 + g) * 68 + kk + t]);
                bf[jn][1] = __float_as_uint(Vs[(n0 + g) * 68 + kk + t + 4]);
            }
#pragma unroll
            for (int im = 0; im < 2; im++)
#pragma unroll
                for (int jn = 0; jn < 4; jn++)
                    MMA_TF32(acc[im][jn], af[im][0], af[im][1], af[im][2], af[im][3],
                             bf[jn][0], bf[jn][1]);
        }
        __syncthreads();
    }

#pragma unroll
    for (int im = 0; im < 2; im++) {
        const int rowA = q0 + wm * 32 + im * 16 + g;
        const int rowB = rowA + 8;
#pragma unroll
        for (int jn = 0; jn < 4; jn++) {
            const int col = h * HDD + wn * 32 + jn * 8 + 2 * t;
            *(float2*)(Ob + (size_t)(b * SS + rowA) * HH + col) =
                make_float2(acc[im][jn][0], acc[im][jn][1]);
            *(float2*)(Ob + (size_t)(b * SS + rowB) * HH + col) =
                make_float2(acc[im][jn][2], acc[im][jn][3]);
        }
    }
}

// ============================================================
// LayerNorm
// ============================================================
__global__ void ln_kernel(const float* __restrict__ X,
                          const float* __restrict__ w,
                          const float* __restrict__ bias,
                          float* __restrict__ Y) {
    __shared__ float red[8];
    __shared__ float bc;
    const int row = blockIdx.x;
    const float* x = X + (size_t)row * HH;
    const int tid = threadIdx.x, lane = tid & 31, warp = tid >> 5;

    float s = 0.f;
    for (int c = tid; c < HH; c += 256) s += x[c];
#pragma unroll
    for (int o = 16; o; o >>= 1) s += __shfl_xor_sync(0xffffffffu, s, o);
    if (lane == 0) red[warp] = s;
    __syncthreads();
    if (tid == 0) {
        float tt = 0.f;
        for (int i = 0; i < 8; i++) tt += red[i];
        bc = tt / HH;
    }
    __syncthreads();
    float mu = bc;

    float v = 0.f;
    for (int c = tid; c < HH; c += 256) { float d = x[c] - mu; v += d * d; }
#pragma unroll
    for (int o = 16; o; o >>= 1) v += __shfl_xor_sync(0xffffffffu, v, o);
    if (lane == 0) red[warp] = v;
    __syncthreads();
    if (tid == 0) {
        float tt = 0.f;
        for (int i = 0; i < 8; i++) tt += red[i];
        bc = rsqrtf(tt / HH + 1e-6f);
    }
    __syncthreads();
    float inv = bc;

    for (int c = tid; c < HH; c += 256)
        Y[(size_t)row * HH + c] = (x[c] - mu) * inv * w[c] + bias[c];
}

// ============================================================
extern "C" void kernel_launch(void* const* d_in, const int* in_sizes, int n_in,
                              void* d_out, int out_size) {
    const float* enc  = (const float*)d_in[0];
    const float* mask = (const float*)d_in[1];
    const float* WQ   = (const float*)d_in[2];
    const float* WK   = (const float*)d_in[3];
    const float* WV   = (const float*)d_in[4];
    const float* WO   = (const float*)d_in[5];
    const float* lnw  = (const float*)d_in[6];
    const float* lnb  = (const float*)d_in[7];

    float* y    = (float*)d_out;              // (B,S,H)
    float* attn = y + (size_t)Y_SIZE;         // (B,NH,S,S)

    float *Qp, *Kp, *Vp, *Op, *Xp;
    cudaGetSymbolAddress((void**)&Qp, g_Q);
    cudaGetSymbolAddress((void**)&Kp, g_K);
    cudaGetSymbolAddress((void**)&Vp, g_V);
    cudaGetSymbolAddress((void**)&Op, g_AO);
    cudaGetSymbolAddress((void**)&Xp, g_X);

    dim3 gt(HH / 128, MM / 128);   // (8, 32)
    gemm_mma_kernel<<<gt, 256>>>(enc, WQ, Qp, nullptr);
    gemm_mma_kernel<<<gt, 256>>>(enc, WK, Kp, nullptr);
    gemm_mma_kernel<<<gt, 256>>>(enc, WV, Vp, nullptr);

    const int sc_smem = 2 * 128 * 68 * (int)sizeof(float);   // 69632
    cudaFuncSetAttribute(scores_mma_kernel,
                         cudaFuncAttributeMaxDynamicSharedMemorySize, sc_smem);
    scores_mma_kernel<<<dim3(SS / 128, SS / 128, BB * NHH), 256, sc_smem>>>(Qp, Kp, mask, attn);

    softmax_kernel<<<BB * NHH * SS, 256>>>(attn);

    const int av_smem = (128 + 64) * 68 * (int)sizeof(float); // 52224
    cudaFuncSetAttribute(av_mma_kernel,
                         cudaFuncAttributeMaxDynamicSharedMemorySize, av_smem);
    av_mma_kernel<<<dim3(SS / 128, BB * NHH), 256, av_smem>>>(attn, Vp, Op);

    gemm_mma_kernel<<<gt, 256>>>(Op, WO, Xp, enc);

    ln_kernel<<<MM, 256>>>(Xp, lnw, lnb, y);
}

// round 5
// speedup vs baseline: 6.1275x; 1.0452x over previous
#include <cuda_runtime.h>
#include <math.h>
#include <stdint.h>

#define BB 2
#define SS 2048
#define HH 1024
#define NHH 16
#define HDD 64
#define MM (BB*SS)          // 4096
#define Y_SIZE (BB*SS*HH)   // 4194304

// ---- scratch (no allocation allowed; device globals) ----
__device__ float g_Q[MM*HH];
__device__ float g_K[MM*HH];
__device__ float g_V[MM*HH];
__device__ float g_AO[MM*HH];
__device__ float g_X[MM*HH];

__device__ __forceinline__ uint32_t f2tf32(float v) {
    uint32_t r;
    asm("cvt.rna.tf32.f32 %0, %1;" : "=r"(r) : "f"(v));
    return r;
}

#define MMA_TF32(acc, a0,a1,a2,a3, b0,b1) \
    asm volatile("mma.sync.aligned.m16n8k8.row.col.f32.tf32.tf32.f32 " \
        "{%0,%1,%2,%3}, {%4,%5,%6,%7}, {%8,%9}, {%0,%1,%2,%3};" \
        : "+f"((acc)[0]), "+f"((acc)[1]), "+f"((acc)[2]), "+f"((acc)[3]) \
        : "r"(a0), "r"(a1), "r"(a2), "r"(a3), "r"(b0), "r"(b1))

// ldmatrix with 32-bit elements viewed as b16 pairs: lane (g=l>>2, t=l&3)
// receives float col t of row g -- exactly the tf32 m16n8k8 fragment layout.
__device__ __forceinline__ void ldsm_x4(uint32_t* r, uint32_t addr) {
    asm volatile("ldmatrix.sync.aligned.m8n8.x4.shared.b16 {%0,%1,%2,%3}, [%4];"
        : "=r"(r[0]), "=r"(r[1]), "=r"(r[2]), "=r"(r[3]) : "r"(addr));
}
__device__ __forceinline__ void ldsm_x2(uint32_t* r, uint32_t addr) {
    asm volatile("ldmatrix.sync.aligned.m8n8.x2.shared.b16 {%0,%1}, [%2];"
        : "=r"(r[0]), "=r"(r[1]) : "r"(addr));
}
// lane-address selectors for ldsm (computed once per thread):
//   rsel: row within 16-row A tile; cA: col offset for x4 (0 or 4)
//   rB:   row within 8-row  B tile; cB: col offset for x2 (0 or 4)
#define LDSM_SELS() \
    const int rsel = (lane & 7) + ((lane >> 3) & 1) * 8; \
    const int cA = (lane >> 4) * 4; \
    const int rB = lane & 7; \
    const int cB = ((lane >> 3) & 1) * 4;

// ============================================================
// tf32 warp-MMA GEMM: C[4096,1024] = A[4096,1024] @ W[1024,1024]^T (+res)
// ============================================================
__global__ void __launch_bounds__(256, 2)
gemm_mma_kernel(const float* __restrict__ A, const float* __restrict__ W,
                float* __restrict__ C, const float* __restrict__ res) {
    __shared__ float As[2][128 * 20];
    __shared__ float Ws[2][128 * 20];
    const int tid = threadIdx.x;
    const int wid = tid >> 5, lane = tid & 31;
    const int wm = wid >> 2, wn = wid & 3;
    const int bm = blockIdx.y * 128, bn = blockIdx.x * 128;
    LDSM_SELS();

    const uint32_t AsU = (uint32_t)__cvta_generic_to_shared(&As[0][0]);
    const uint32_t WsU = (uint32_t)__cvta_generic_to_shared(&Ws[0][0]);
    int rowA[4], rowB[4];
#pragma unroll
    for (int im = 0; im < 4; im++) rowA[im] = (wm * 64 + im * 16 + rsel) * 20 + cA;
#pragma unroll
    for (int jn = 0; jn < 4; jn++) rowB[jn] = (wn * 32 + jn * 8 + rB) * 20 + cB;

    const int p0 = tid, p1 = tid + 256;
    const int r0 = p0 >> 2, q0 = (p0 & 3) * 4;
    const int r1 = p1 >> 2, q1 = (p1 & 3) * 4;
    const float* Arow0 = A + (size_t)(bm + r0) * 1024 + q0;
    const float* Arow1 = A + (size_t)(bm + r1) * 1024 + q1;
    const float* Wrow0 = W + (size_t)(bn + r0) * 1024 + q0;
    const float* Wrow1 = W + (size_t)(bn + r1) * 1024 + q1;
    const int s0 = r0 * 20 + q0, s1 = r1 * 20 + q1;

    float acc[4][4][4];
#pragma unroll
    for (int i = 0; i < 4; i++)
#pragma unroll
        for (int j = 0; j < 4; j++)
#pragma unroll
            for (int q = 0; q < 4; q++) acc[i][j][q] = 0.f;

    {
        float4 va0 = *(const float4*)(Arow0);
        float4 va1 = *(const float4*)(Arow1);
        float4 vw0 = *(const float4*)(Wrow0);
        float4 vw1 = *(const float4*)(Wrow1);
        uint32_t* a0 = (uint32_t*)&As[0][s0];
        a0[0]=f2tf32(va0.x); a0[1]=f2tf32(va0.y); a0[2]=f2tf32(va0.z); a0[3]=f2tf32(va0.w);
        uint32_t* a1 = (uint32_t*)&As[0][s1];
        a1[0]=f2tf32(va1.x); a1[1]=f2tf32(va1.y); a1[2]=f2tf32(va1.z); a1[3]=f2tf32(va1.w);
        uint32_t* w0 = (uint32_t*)&Ws[0][s0];
        w0[0]=f2tf32(vw0.x); w0[1]=f2tf32(vw0.y); w0[2]=f2tf32(vw0.z); w0[3]=f2tf32(vw0.w);
        uint32_t* w1 = (uint32_t*)&Ws[0][s1];
        w1[0]=f2tf32(vw1.x); w1[1]=f2tf32(vw1.y); w1[2]=f2tf32(vw1.z); w1[3]=f2tf32(vw1.w);
    }
    __syncthreads();

    for (int c = 0; c < 64; c++) {
        const int buf = c & 1;
        const uint32_t aBuf = AsU + (uint32_t)buf * (128 * 20 * 4);
        const uint32_t wBuf = WsU + (uint32_t)buf * (128 * 20 * 4);
        float4 ra0, ra1, rw0, rw1;
        if (c < 63) {
            const int k0 = (c + 1) * 16;
            ra0 = *(const float4*)(Arow0 + k0);
            ra1 = *(const float4*)(Arow1 + k0);
            rw0 = *(const float4*)(Wrow0 + k0);
            rw1 = *(const float4*)(Wrow1 + k0);
        }

#pragma unroll
        for (int ks = 0; ks < 2; ks++) {
            const int kk = ks * 8;
            uint32_t af[4][4], bf[4][2];
#pragma unroll
            for (int im = 0; im < 4; im++)
                ldsm_x4(af[im], aBuf + (uint32_t)(rowA[im] + kk) * 4);
#pragma unroll
            for (int jn = 0; jn < 4; jn++)
                ldsm_x2(bf[jn], wBuf + (uint32_t)(rowB[jn] + kk) * 4);
#pragma unroll
            for (int im = 0; im < 4; im++)
#pragma unroll
                for (int jn = 0; jn < 4; jn++)
                    MMA_TF32(acc[im][jn], af[im][0], af[im][1], af[im][2], af[im][3],
                             bf[jn][0], bf[jn][1]);
        }

        if (c < 63) {
            const int nxt = buf ^ 1;
            uint32_t* a0 = (uint32_t*)&As[nxt][s0];
            a0[0]=f2tf32(ra0.x); a0[1]=f2tf32(ra0.y); a0[2]=f2tf32(ra0.z); a0[3]=f2tf32(ra0.w);
            uint32_t* a1 = (uint32_t*)&As[nxt][s1];
            a1[0]=f2tf32(ra1.x); a1[1]=f2tf32(ra1.y); a1[2]=f2tf32(ra1.z); a1[3]=f2tf32(ra1.w);
            uint32_t* w0 = (uint32_t*)&Ws[nxt][s0];
            w0[0]=f2tf32(rw0.x); w0[1]=f2tf32(rw0.y); w0[2]=f2tf32(rw0.z); w0[3]=f2tf32(rw0.w);
            uint32_t* w1 = (uint32_t*)&Ws[nxt][s1];
            w1[0]=f2tf32(rw1.x); w1[1]=f2tf32(rw1.y); w1[2]=f2tf32(rw1.z); w1[3]=f2tf32(rw1.w);
        }
        __syncthreads();
    }

    const int g = lane >> 2, t = lane & 3;
#pragma unroll
    for (int im = 0; im < 4; im++) {
        const int rowAo = bm + wm * 64 + im * 16 + g;
        const int rowBo = rowAo + 8;
#pragma unroll
        for (int jn = 0; jn < 4; jn++) {
            const int col = bn + wn * 32 + jn * 8 + 2 * t;
            float2 vA = make_float2(acc[im][jn][0], acc[im][jn][1]);
            float2 vB = make_float2(acc[im][jn][2], acc[im][jn][3]);
            if (res) {
                float2 rA = *(const float2*)(res + (size_t)rowAo * 1024 + col);
                float2 rB2 = *(const float2*)(res + (size_t)rowBo * 1024 + col);
                vA.x += rA.x; vA.y += rA.y; vB.x += rB2.x; vB.y += rB2.y;
            }
            *(float2*)(C + (size_t)rowAo * 1024 + col) = vA;
            *(float2*)(C + (size_t)rowBo * 1024 + col) = vB;
        }
    }
}

// ============================================================
// Scores via MMA: raw = (Q K^T)*0.125 with mask -> attn buffer (unnormalized).
// ============================================================
__global__ void __launch_bounds__(256, 2)
scores_mma_kernel(const float* __restrict__ Qb, const float* __restrict__ Kb,
                  const float* __restrict__ mask, float* __restrict__ attn) {
    extern __shared__ float sm[];
    float* Qs = sm;               // 128 x 68
    float* Ks = sm + 128 * 68;    // 128 x 68
    const int tid = threadIdx.x;
    const int wid = tid >> 5, lane = tid & 31;
    const int wm = wid >> 2, wn = wid & 3;
    const int bh = blockIdx.z, b = bh >> 4, h = bh & 15;
    const int q0 = blockIdx.y * 128, n0b = blockIdx.x * 128;
    LDSM_SELS();

    const uint32_t QsU = (uint32_t)__cvta_generic_to_shared(Qs);
    const uint32_t KsU = (uint32_t)__cvta_generic_to_shared(Ks);
    int rowA[4], rowB[4];
#pragma unroll
    for (int im = 0; im < 4; im++) rowA[im] = (wm * 64 + im * 16 + rsel) * 68 + cA;
#pragma unroll
    for (int jn = 0; jn < 4; jn++) rowB[jn] = (wn * 32 + jn * 8 + rB) * 68 + cB;

    const float* Qbase = Qb + ((size_t)(b * SS + q0)) * HH + h * HDD;
    const float* Kbase = Kb + ((size_t)(b * SS + n0b)) * HH + h * HDD;
#pragma unroll
    for (int j = 0; j < 8; j++) {
        int idx = tid + j * 256;
        int r = idx >> 4, c4 = (idx & 15) * 4;
        float4 vq = *(const float4*)(Qbase + (size_t)r * HH + c4);
        uint32_t* q = (uint32_t*)&Qs[r * 68 + c4];
        q[0]=f2tf32(vq.x); q[1]=f2tf32(vq.y); q[2]=f2tf32(vq.z); q[3]=f2tf32(vq.w);
        float4 vk = *(const float4*)(Kbase + (size_t)r * HH + c4);
        uint32_t* k = (uint32_t*)&Ks[r * 68 + c4];
        k[0]=f2tf32(vk.x); k[1]=f2tf32(vk.y); k[2]=f2tf32(vk.z); k[3]=f2tf32(vk.w);
    }
    __syncthreads();

    float acc[4][4][4];
#pragma unroll
    for (int i = 0; i < 4; i++)
#pragma unroll
        for (int j = 0; j < 4; j++)
#pragma unroll
            for (int q = 0; q < 4; q++) acc[i][j][q] = 0.f;

#pragma unroll
    for (int ks = 0; ks < 8; ks++) {
        const int kk = ks * 8;
        uint32_t af[4][4], bf[4][2];
#pragma unroll
        for (int im = 0; im < 4; im++)
            ldsm_x4(af[im], QsU + (uint32_t)(rowA[im] + kk) * 4);
#pragma unroll
        for (int jn = 0; jn < 4; jn++)
            ldsm_x2(bf[jn], KsU + (uint32_t)(rowB[jn] + kk) * 4);
#pragma unroll
        for (int im = 0; im < 4; im++)
#pragma unroll
            for (int jn = 0; jn < 4; jn++)
                MMA_TF32(acc[im][jn], af[im][0], af[im][1], af[im][2], af[im][3],
                         bf[jn][0], bf[jn][1]);
    }

    const int g = lane >> 2, t = lane & 3;
#pragma unroll
    for (int im = 0; im < 4; im++) {
        const int rowAo = q0 + wm * 64 + im * 16 + g;
        const int rowBo = rowAo + 8;
        const float* mA = mask + ((size_t)(b * SS + rowAo)) * SS + n0b;
        const float* mB = mask + ((size_t)(b * SS + rowBo)) * SS + n0b;
        float* aA = attn + ((size_t)((b * NHH + h) * SS + rowAo)) * SS + n0b;
        float* aB = attn + ((size_t)((b * NHH + h) * SS + rowBo)) * SS + n0b;
#pragma unroll
        for (int jn = 0; jn < 4; jn++) {
            const int col = wn * 32 + jn * 8 + 2 * t;
            float2 mvA = *(const float2*)(mA + col);
            float2 mvB = *(const float2*)(mB + col);
            float2 vA, vB;
            vA.x = (mvA.x == 0.f) ? -1e9f : acc[im][jn][0] * 0.125f;
            vA.y = (mvA.y == 0.f) ? -1e9f : acc[im][jn][1] * 0.125f;
            vB.x = (mvB.x == 0.f) ? -1e9f : acc[im][jn][2] * 0.125f;
            vB.y = (mvB.y == 0.f) ? -1e9f : acc[im][jn][3] * 0.125f;
            *(float2*)(aA + col) = vA;
            *(float2*)(aB + col) = vB;
        }
    }
}

// ============================================================
// Row softmax in-place on attn
// ============================================================
__global__ void __launch_bounds__(256, 8)
softmax_kernel(float* __restrict__ attn) {
    __shared__ float red[8];
    float* p = attn + (size_t)blockIdx.x * SS;
    const int tid = threadIdx.x, lane = tid & 31, warp = tid >> 5;

    float4 v0 = *(const float4*)(p + tid * 4);
    float4 v1 = *(const float4*)(p + 1024 + tid * 4);

    float mx = fmaxf(fmaxf(fmaxf(v0.x, v0.y), fmaxf(v0.z, v0.w)),
                     fmaxf(fmaxf(v1.x, v1.y), fmaxf(v1.z, v1.w)));
#pragma unroll
    for (int o = 16; o; o >>= 1) mx = fmaxf(mx, __shfl_xor_sync(0xffffffffu, mx, o));
    if (lane == 0) red[warp] = mx;
    __syncthreads();
    float m = red[0];
#pragma unroll
    for (int i = 1; i < 8; i++) m = fmaxf(m, red[i]);

    v0.x = __expf(v0.x - m); v0.y = __expf(v0.y - m);
    v0.z = __expf(v0.z - m); v0.w = __expf(v0.w - m);
    v1.x = __expf(v1.x - m); v1.y = __expf(v1.y - m);
    v1.z = __expf(v1.z - m); v1.w = __expf(v1.w - m);

    float s = v0.x + v0.y + v0.z + v0.w + v1.x + v1.y + v1.z + v1.w;
#pragma unroll
    for (int o = 16; o; o >>= 1) s += __shfl_xor_sync(0xffffffffu, s, o);
    __syncthreads();
    if (lane == 0) red[warp] = s;
    __syncthreads();
    float tot = 0.f;
#pragma unroll
    for (int i = 0; i < 8; i++) tot += red[i];
    float inv = 1.f / tot;

    v0.x *= inv; v0.y *= inv; v0.z *= inv; v0.w *= inv;
    v1.x *= inv; v1.y *= inv; v1.z *= inv; v1.w *= inv;
    *(float4*)(p + tid * 4) = v0;
    *(float4*)(p + 1024 + tid * 4) = v1;
}

// ============================================================
// AV via MMA: O[128q x 64d] per block, K streamed in 64-chunks.
// ============================================================
__global__ void __launch_bounds__(256, 3)
av_mma_kernel(const float* __restrict__ attn, const float* __restrict__ Vb,
              float* __restrict__ Ob) {
    extern __shared__ float sm[];
    float* Ps = sm;               // 128 x 68
    float* Vs = sm + 128 * 68;    // 64 x 68  ([d][k])
    const int tid = threadIdx.x;
    const int wid = tid >> 5, lane = tid & 31;
    const int wm = wid >> 1, wn = wid & 1;       // 4 x 2
    const int bh = blockIdx.y, b = bh >> 4, h = bh & 15;
    const int q0 = blockIdx.x * 128;
    LDSM_SELS();

    const uint32_t PsU = (uint32_t)__cvta_generic_to_shared(Ps);
    const uint32_t VsU = (uint32_t)__cvta_generic_to_shared(Vs);
    int rowA[2], rowB[4];
#pragma unroll
    for (int im = 0; im < 2; im++) rowA[im] = (wm * 32 + im * 16 + rsel) * 68 + cA;
#pragma unroll
    for (int jn = 0; jn < 4; jn++) rowB[jn] = (wn * 32 + jn * 8 + rB) * 68 + cB;

    float acc[2][4][4];
#pragma unroll
    for (int i = 0; i < 2; i++)
#pragma unroll
        for (int j = 0; j < 4; j++)
#pragma unroll
            for (int q = 0; q < 4; q++) acc[i][j][q] = 0.f;

    const float* Pbase = attn + ((size_t)((b * NHH + h) * SS + q0)) * SS;
    const float* Vbase = Vb + ((size_t)(b * SS)) * HH + h * HDD;

    for (int k0 = 0; k0 < SS; k0 += 64) {
#pragma unroll
        for (int j = 0; j < 8; j++) {
            int idx = tid + j * 256;
            int r = idx >> 4, c4 = (idx & 15) * 4;
            float4 v = *(const float4*)(Pbase + (size_t)r * SS + k0 + c4);
            uint32_t* q = (uint32_t*)&Ps[r * 68 + c4];
            q[0]=f2tf32(v.x); q[1]=f2tf32(v.y); q[2]=f2tf32(v.z); q[3]=f2tf32(v.w);
        }
#pragma unroll
        for (int j = 0; j < 4; j++) {
            int idx = tid + j * 256;
            int r = idx >> 4, c4 = (idx & 15) * 4;   // r = k row, c4 = d col
            float4 v = *(const float4*)(Vbase + (size_t)(k0 + r) * HH + c4);
            Vs[(c4 + 0) * 68 + r] = __uint_as_float(f2tf32(v.x));
            Vs[(c4 + 1) * 68 + r] = __uint_as_float(f2tf32(v.y));
            Vs[(c4 + 2) * 68 + r] = __uint_as_float(f2tf32(v.z));
            Vs[(c4 + 3) * 68 + r] = __uint_as_float(f2tf32(v.w));
        }
        __syncthreads();

#pragma unroll
        for (int ks = 0; ks < 8; ks++) {
            const int kk = ks * 8;
            uint32_t af[2][4], bf[4][2];
#pragma unroll
            for (int im = 0; im < 2; im++)
                ldsm_x4(af[im], PsU + (uint32_t)(rowA[im] + kk) * 4);
#pragma unroll
            for (int jn = 0; jn < 4; jn++)
                ldsm_x2(bf[jn], VsU + (uint32_t)(rowB[jn] + kk) * 4);
#pragma unroll
            for (int im = 0; im < 2; im++)
#pragma unroll
                for (int jn = 0; jn < 4; jn++)
                    MMA_TF32(acc[im][jn], af[im][0], af[im][1], af[im][2], af[im][3],
                             bf[jn][0], bf[jn][1]);
        }
        __syncthreads();
    }

    const int g = lane >> 2, t = lane & 3;
#pragma unroll
    for (int im = 0; im < 2; im++) {
        const int rowAo = q0 + wm * 32 + im * 16 + g;
        const int rowBo = rowAo + 8;
#pragma unroll
        for (int jn = 0; jn < 4; jn++) {
            const int col = h * HDD + wn * 32 + jn * 8 + 2 * t;
            *(float2*)(Ob + (size_t)(b * SS + rowAo) * HH + col) =
                make_float2(acc[im][jn][0], acc[im][jn][1]);
            *(float2*)(Ob + (size_t)(b * SS + rowBo) * HH + col) =
                make_float2(acc[im][jn][2], acc[im][jn][3]);
        }
    }
}

// ============================================================
// LayerNorm
// ============================================================
__global__ void ln_kernel(const float* __restrict__ X,
                          const float* __restrict__ w,
                          const float* __restrict__ bias,
                          float* __restrict__ Y) {
    __shared__ float red[8];
    __shared__ float bc;
    const int row = blockIdx.x;
    const float* x = X + (size_t)row * HH;
    const int tid = threadIdx.x, lane = tid & 31, warp = tid >> 5;

    float s = 0.f;
    for (int c = tid; c < HH; c += 256) s += x[c];
#pragma unroll
    for (int o = 16; o; o >>= 1) s += __shfl_xor_sync(0xffffffffu, s, o);
    if (lane == 0) red[warp] = s;
    __syncthreads();
    if (tid == 0) {
        float tt = 0.f;
        for (int i = 0; i < 8; i++) tt += red[i];
        bc = tt / HH;
    }
    __syncthreads();
    float mu = bc;

    float v = 0.f;
    for (int c = tid; c < HH; c += 256) { float d = x[c] - mu; v += d * d; }
#pragma unroll
    for (int o = 16; o; o >>= 1) v += __shfl_xor_sync(0xffffffffu, v, o);
    if (lane == 0) red[warp] = v;
    __syncthreads();
    if (tid == 0) {
        float tt = 0.f;
        for (int i = 0; i < 8; i++) tt += red[i];
        bc = rsqrtf(tt / HH + 1e-6f);
    }
    __syncthreads();
    float inv = bc;

    for (int c = tid; c < HH; c += 256)
        Y[(size_t)row * HH + c] = (x[c] - mu) * inv * w[c] + bias[c];
}

// ============================================================
extern "C" void kernel_launch(void* const* d_in, const int* in_sizes, int n_in,
                              void* d_out, int out_size) {
    const float* enc  = (const float*)d_in[0];
    const float* mask = (const float*)d_in[1];
    const float* WQ   = (const float*)d_in[2];
    const float* WK   = (const float*)d_in[3];
    const float* WV   = (const float*)d_in[4];
    const float* WO   = (const float*)d_in[5];
    const float* lnw  = (const float*)d_in[6];
    const float* lnb  = (const float*)d_in[7];

    float* y    = (float*)d_out;              // (B,S,H)
    float* attn = y + (size_t)Y_SIZE;         // (B,NH,S,S)

    float *Qp, *Kp, *Vp, *Op, *Xp;
    cudaGetSymbolAddress((void**)&Qp, g_Q);
    cudaGetSymbolAddress((void**)&Kp, g_K);
    cudaGetSymbolAddress((void**)&Vp, g_V);
    cudaGetSymbolAddress((void**)&Op, g_AO);
    cudaGetSymbolAddress((void**)&Xp, g_X);

    dim3 gt(HH / 128, MM / 128);   // (8, 32)
    gemm_mma_kernel<<<gt, 256>>>(enc, WQ, Qp, nullptr);
    gemm_mma_kernel<<<gt, 256>>>(enc, WK, Kp, nullptr);
    gemm_mma_kernel<<<gt, 256>>>(enc, WV, Vp, nullptr);

    const int sc_smem = 2 * 128 * 68 * (int)sizeof(float);   // 69632
    cudaFuncSetAttribute(scores_mma_kernel,
                         cudaFuncAttributeMaxDynamicSharedMemorySize, sc_smem);
    scores_mma_kernel<<<dim3(SS / 128, SS / 128, BB * NHH), 256, sc_smem>>>(Qp, Kp, mask, attn);

    softmax_kernel<<<BB * NHH * SS, 256>>>(attn);

    const int av_smem = (128 + 64) * 68 * (int)sizeof(float); // 52224
    cudaFuncSetAttribute(av_mma_kernel,
                         cudaFuncAttributeMaxDynamicSharedMemorySize, av_smem);
    av_mma_kernel<<<dim3(SS / 128, BB * NHH), 256, av_smem>>>(attn, Vp, Op);

    gemm_mma_kernel<<<gt, 256>>>(Op, WO, Xp, enc);

    ln_kernel<<<MM, 256>>>(Xp, lnw, lnb, y);
}